// round 1
// baseline (speedup 1.0000x reference)
#include <cuda_runtime.h>
#include <math.h>

#define BATCH  2
#define CH     512
#define NPIX   4096      // 64*64
#define GROUPS 32
#define CPG    (CH/GROUPS)   // 16
#define EPS    1e-6f

// ---------------- scratch (device globals; no allocation) ----------------
__device__ float g_hn[(size_t)BATCH*CH*NPIX];
__device__ float g_q [(size_t)BATCH*CH*NPIX];
__device__ float g_k [(size_t)BATCH*CH*NPIX];
__device__ float g_v [(size_t)BATCH*CH*NPIX];
__device__ float g_o [(size_t)BATCH*CH*NPIX];
__device__ float g_s [(size_t)BATCH*NPIX*NPIX];   // scores / attn (128 MiB)

// ---------------- GroupNorm ----------------
// grid: (GROUPS, BATCH), block: 256
__global__ void gn_kernel(const float* __restrict__ x,
                          const float* __restrict__ gamma,
                          const float* __restrict__ beta)
{
    const int b = blockIdx.y, g = blockIdx.x;
    const size_t base = ((size_t)b*CH + (size_t)g*CPG) * NPIX;
    const float* xp = x + base;
    float* hp = g_hn + base;
    const int NE = CPG * NPIX; // 65536

    float s = 0.f, ss = 0.f;
    for (int i = threadIdx.x*4; i < NE; i += blockDim.x*4) {
        float4 v = *(const float4*)(xp + i);
        s  += v.x + v.y + v.z + v.w;
        ss += v.x*v.x + v.y*v.y + v.z*v.z + v.w*v.w;
    }
    __shared__ float sh1[256], sh2[256];
    sh1[threadIdx.x] = s; sh2[threadIdx.x] = ss;
    __syncthreads();
    for (int o = 128; o > 0; o >>= 1) {
        if (threadIdx.x < o) {
            sh1[threadIdx.x] += sh1[threadIdx.x + o];
            sh2[threadIdx.x] += sh2[threadIdx.x + o];
        }
        __syncthreads();
    }
    const float mu  = sh1[0] / (float)NE;
    const float var = sh2[0] / (float)NE - mu*mu;
    const float inv = rsqrtf(var + EPS);

    for (int i = threadIdx.x*4; i < NE; i += blockDim.x*4) {
        int c = g*CPG + i / NPIX;          // constant within the float4 (NPIX % 4 == 0)
        float ga = gamma[c], be = beta[c];
        float4 v = *(const float4*)(xp + i);
        v.x = (v.x - mu)*inv*ga + be;
        v.y = (v.y - mu)*inv*ga + be;
        v.z = (v.z - mu)*inv*ga + be;
        v.w = (v.w - mu)*inv*ga + be;
        *(float4*)(hp + i) = v;
    }
}

// ---------------- generic tiled SGEMM ----------------
// MODE 0 (NN): A[M,K] row-major, B[K,N] row-major
// MODE 1 (TN): A[K,M] row-major (C[m,n]=sum_k A[k,m]*B[k,n]), B[K,N]
// MODE 2 (NT): A[M,K], B[N,K] row-major (C[m,n]=sum_k A[m,k]*B[n,k])
// block tile 64x64, K-step 16, 16x16 threads, 4x4 per thread.
// All dims assumed multiples of tile sizes (true for this problem).
template<int MODE, bool BIAS, bool RESID>
__global__ void gemm_k(const float* __restrict__ A,
                       const float* __restrict__ B,
                       float* __restrict__ Cm,
                       const float* __restrict__ bias,
                       const float* __restrict__ resid,
                       int M, int N, int K,
                       size_t sA, size_t sB, size_t sC,
                       float alpha)
{
    __shared__ float As[16][64];
    __shared__ float Bs[16][64];

    const int bz = blockIdx.z;
    A  += sA * bz;
    B  += sB * bz;
    Cm += sC * bz;
    const float* res = RESID ? (resid + sC * bz) : nullptr;

    const int m0 = blockIdx.y * 64;
    const int n0 = blockIdx.x * 64;
    const int tx = threadIdx.x, ty = threadIdx.y;     // 16 x 16
    const int tid = ty * 16 + tx;

    float acc[4][4] = {};

    for (int k0 = 0; k0 < K; k0 += 16) {
        // ---- load A tile into As[k][m] ----
        if (MODE == 0 || MODE == 2) {                 // A[M,K]
            int row  = tid >> 2;                      // 0..63
            int kseg = (tid & 3) * 4;
            float4 v = *(const float4*)(A + (size_t)(m0 + row)*K + k0 + kseg);
            As[kseg+0][row] = v.x; As[kseg+1][row] = v.y;
            As[kseg+2][row] = v.z; As[kseg+3][row] = v.w;
        } else {                                      // MODE 1: A[K,M]
            int kk   = tid >> 4;                      // 0..15
            int mseg = (tid & 15) * 4;
            float4 v = *(const float4*)(A + (size_t)(k0 + kk)*M + m0 + mseg);
            *(float4*)&As[kk][mseg] = v;
        }
        // ---- load B tile into Bs[k][n] ----
        if (MODE == 0 || MODE == 1) {                 // B[K,N]
            int kk   = tid >> 4;
            int nseg = (tid & 15) * 4;
            float4 v = *(const float4*)(B + (size_t)(k0 + kk)*N + n0 + nseg);
            *(float4*)&Bs[kk][nseg] = v;
        } else {                                      // MODE 2: B[N,K]
            int nn   = tid >> 2;                      // 0..63
            int kseg = (tid & 3) * 4;
            float4 v = *(const float4*)(B + (size_t)(n0 + nn)*K + k0 + kseg);
            Bs[kseg+0][nn] = v.x; Bs[kseg+1][nn] = v.y;
            Bs[kseg+2][nn] = v.z; Bs[kseg+3][nn] = v.w;
        }
        __syncthreads();

        #pragma unroll
        for (int kk = 0; kk < 16; kk++) {
            float4 a = *(const float4*)&As[kk][ty*4];
            float4 b = *(const float4*)&Bs[kk][tx*4];
            float av[4] = {a.x, a.y, a.z, a.w};
            float bv[4] = {b.x, b.y, b.z, b.w};
            #pragma unroll
            for (int i = 0; i < 4; i++)
                #pragma unroll
                for (int j = 0; j < 4; j++)
                    acc[i][j] += av[i] * bv[j];
        }
        __syncthreads();
    }

    #pragma unroll
    for (int i = 0; i < 4; i++) {
        int m = m0 + ty*4 + i;
        float bia = BIAS ? bias[m] : 0.f;
        #pragma unroll
        for (int j = 0; j < 4; j++) {
            int n = n0 + tx*4 + j;
            float c = acc[i][j] * alpha + bia;
            if (RESID) c += res[(size_t)m*N + n];
            Cm[(size_t)m*N + n] = c;
        }
    }
}

// ---------------- row softmax over g_s ----------------
// grid: BATCH*NPIX blocks (one per row), block: 256
__global__ void softmax_kernel()
{
    float* p = g_s + (size_t)blockIdx.x * NPIX;
    const int t = threadIdx.x;
    __shared__ float sh[256];

    float m = -1e30f;
    for (int i = t*4; i < NPIX; i += 1024) {
        float4 v = *(const float4*)(p + i);
        m = fmaxf(m, fmaxf(fmaxf(v.x, v.y), fmaxf(v.z, v.w)));
    }
    sh[t] = m; __syncthreads();
    for (int o = 128; o > 0; o >>= 1) {
        if (t < o) sh[t] = fmaxf(sh[t], sh[t+o]);
        __syncthreads();
    }
    m = sh[0]; __syncthreads();

    float s = 0.f;
    for (int i = t*4; i < NPIX; i += 1024) {
        float4 v = *(const float4*)(p + i);
        v.x = __expf(v.x - m); v.y = __expf(v.y - m);
        v.z = __expf(v.z - m); v.w = __expf(v.w - m);
        s += v.x + v.y + v.z + v.w;
        *(float4*)(p + i) = v;
    }
    sh[t] = s; __syncthreads();
    for (int o = 128; o > 0; o >>= 1) {
        if (t < o) sh[t] += sh[t+o];
        __syncthreads();
    }
    const float inv = 1.f / sh[0];

    for (int i = t*4; i < NPIX; i += 1024) {
        float4 v = *(const float4*)(p + i);
        v.x *= inv; v.y *= inv; v.z *= inv; v.w *= inv;
        *(float4*)(p + i) = v;
    }
}

// ---------------- launch ----------------
extern "C" void kernel_launch(void* const* d_in, const int* in_sizes, int n_in,
                              void* d_out, int out_size)
{
    const float* x     = (const float*)d_in[0];
    const float* gamma = (const float*)d_in[1];
    const float* beta  = (const float*)d_in[2];
    const float* wq    = (const float*)d_in[3];
    const float* bq    = (const float*)d_in[4];
    const float* wk    = (const float*)d_in[5];
    const float* bk    = (const float*)d_in[6];
    const float* wv    = (const float*)d_in[7];
    const float* bv    = (const float*)d_in[8];
    const float* wo    = (const float*)d_in[9];
    const float* bo    = (const float*)d_in[10];
    float* out = (float*)d_out;

    float *p_hn, *p_q, *p_k, *p_v, *p_o, *p_s;
    cudaGetSymbolAddress((void**)&p_hn, g_hn);
    cudaGetSymbolAddress((void**)&p_q,  g_q);
    cudaGetSymbolAddress((void**)&p_k,  g_k);
    cudaGetSymbolAddress((void**)&p_v,  g_v);
    cudaGetSymbolAddress((void**)&p_o,  g_o);
    cudaGetSymbolAddress((void**)&p_s,  g_s);

    const size_t sBC = (size_t)CH * NPIX;        // per-batch stride for [C, N] tensors
    const size_t sS  = (size_t)NPIX * NPIX;      // per-batch stride for scores
    const float scale = rsqrtf((float)CH);

    // 1. GroupNorm
    gn_kernel<<<dim3(GROUPS, BATCH), 256>>>(x, gamma, beta);

    dim3 thr(16, 16);

    // 2. q/k/v = W * hn + b   (NN: M=CH, N=NPIX, K=CH)
    dim3 gQKV(NPIX/64, CH/64, BATCH);
    gemm_k<0, true, false><<<gQKV, thr>>>(wq, p_hn, p_q, bq, nullptr,
                                          CH, NPIX, CH, 0, sBC, sBC, 1.f);
    gemm_k<0, true, false><<<gQKV, thr>>>(wk, p_hn, p_k, bk, nullptr,
                                          CH, NPIX, CH, 0, sBC, sBC, 1.f);
    gemm_k<0, true, false><<<gQKV, thr>>>(wv, p_hn, p_v, bv, nullptr,
                                          CH, NPIX, CH, 0, sBC, sBC, 1.f);

    // 3. scores = scale * q^T k  (TN: M=NPIX, N=NPIX, K=CH)
    dim3 gS(NPIX/64, NPIX/64, BATCH);
    gemm_k<1, false, false><<<gS, thr>>>(p_q, p_k, p_s, nullptr, nullptr,
                                         NPIX, NPIX, CH, sBC, sBC, sS, scale);

    // 4. softmax rows
    softmax_kernel<<<BATCH*NPIX, 256>>>();

    // 5. o = v * attn^T  (NT: M=CH, N=NPIX, K=NPIX)
    dim3 gO(NPIX/64, CH/64, BATCH);
    gemm_k<2, false, false><<<gO, thr>>>(p_v, p_s, p_o, nullptr, nullptr,
                                         CH, NPIX, NPIX, sBC, sS, sBC, 1.f);

    // 6. out = wo * o + bo + x  (NN with residual)
    gemm_k<0, true, true><<<gQKV, thr>>>(wo, p_o, out, bo, x,
                                         CH, NPIX, CH, 0, sBC, sBC, 1.f);
}

// round 2
// speedup vs baseline: 2.3793x; 2.3793x over previous
#include <cuda_runtime.h>
#include <math.h>
#include <stdint.h>

#define BATCH  2
#define CH     512
#define NPIX   4096      // 64*64
#define GROUPS 32
#define CPG    (CH/GROUPS)   // 16
#define EPS    1e-6f

// ---------------- scratch (device globals; no allocation) ----------------
__device__ float g_hn[(size_t)BATCH*CH*NPIX];
__device__ float g_q [(size_t)BATCH*CH*NPIX];
__device__ float g_k [(size_t)BATCH*CH*NPIX];
__device__ float g_v [(size_t)BATCH*CH*NPIX];
__device__ float g_o [(size_t)BATCH*CH*NPIX];
__device__ float g_s [(size_t)BATCH*NPIX*NPIX];   // scores / attn (128 MiB)

// ---------------- GroupNorm ----------------
__global__ void gn_kernel(const float* __restrict__ x,
                          const float* __restrict__ gamma,
                          const float* __restrict__ beta)
{
    const int b = blockIdx.y, g = blockIdx.x;
    const size_t base = ((size_t)b*CH + (size_t)g*CPG) * NPIX;
    const float* xp = x + base;
    float* hp = g_hn + base;
    const int NE = CPG * NPIX; // 65536

    float s = 0.f, ss = 0.f;
    for (int i = threadIdx.x*4; i < NE; i += blockDim.x*4) {
        float4 v = *(const float4*)(xp + i);
        s  += v.x + v.y + v.z + v.w;
        ss += v.x*v.x + v.y*v.y + v.z*v.z + v.w*v.w;
    }
    __shared__ float sh1[256], sh2[256];
    sh1[threadIdx.x] = s; sh2[threadIdx.x] = ss;
    __syncthreads();
    for (int o = 128; o > 0; o >>= 1) {
        if (threadIdx.x < o) {
            sh1[threadIdx.x] += sh1[threadIdx.x + o];
            sh2[threadIdx.x] += sh2[threadIdx.x + o];
        }
        __syncthreads();
    }
    const float mu  = sh1[0] / (float)NE;
    const float var = sh2[0] / (float)NE - mu*mu;
    const float inv = rsqrtf(var + EPS);

    for (int i = threadIdx.x*4; i < NE; i += blockDim.x*4) {
        int c = g*CPG + i / NPIX;
        float ga = gamma[c], be = beta[c];
        float4 v = *(const float4*)(xp + i);
        v.x = (v.x - mu)*inv*ga + be;
        v.y = (v.y - mu)*inv*ga + be;
        v.z = (v.z - mu)*inv*ga + be;
        v.w = (v.w - mu)*inv*ga + be;
        *(float4*)(hp + i) = v;
    }
}

// ---------------- tf32 helpers ----------------
__device__ __forceinline__ uint32_t f2tf(float x) {
    uint32_t r;
    asm("cvt.rna.tf32.f32 %0, %1;" : "=r"(r) : "f"(x));
    return r;
}

__device__ __forceinline__ void mma_tf32(float* c, const uint32_t* a, const uint32_t* b) {
    asm volatile(
        "mma.sync.aligned.m16n8k8.row.col.f32.tf32.tf32.f32 "
        "{%0,%1,%2,%3}, {%4,%5,%6,%7}, {%8,%9}, {%0,%1,%2,%3};"
        : "+f"(c[0]), "+f"(c[1]), "+f"(c[2]), "+f"(c[3])
        : "r"(a[0]), "r"(a[1]), "r"(a[2]), "r"(a[3]),
          "r"(b[0]), "r"(b[1]));
}

// ---------------- tensor-core tf32 GEMM ----------------
// C[m,n] = alpha * sum_k Aop[m,k]*Bop[k,n]  (+bias[m]) (+resid[m,n])
// MODE 0 (NN): A[M,K], B[K,N]
// MODE 1 (TN): A[K,M], B[K,N]
// MODE 2 (NT): A[M,K], B[N,K]
// Block tile 128x128, BK=16, 256 threads (8 warps, 2x4 m-by-n), warp tile 64x32.
// All dims multiples of tile sizes (true here).
#define SPAD 132
template<int MODE, bool BIAS, bool RESID>
__global__ __launch_bounds__(256, 2)
void gemm_tc(const float* __restrict__ A,
             const float* __restrict__ B,
             float* __restrict__ Cm,
             const float* __restrict__ bias,
             const float* __restrict__ resid,
             int M, int N, int K,
             size_t sA, size_t sB, size_t sC,
             float alpha)
{
    __shared__ uint32_t As[2][16][SPAD];
    __shared__ uint32_t Bs[2][16][SPAD];

    const int bz = blockIdx.z;
    A  += sA * bz;
    B  += sB * bz;
    Cm += sC * bz;
    const float* res = RESID ? (resid + sC * bz) : nullptr;

    const int m0 = blockIdx.y * 128;
    const int n0 = blockIdx.x * 128;
    const int tid  = threadIdx.x;
    const int lane = tid & 31;
    const int warp = tid >> 5;
    const int wm = (warp & 1) * 64;    // warp m-offset in tile
    const int wn = (warp >> 1) * 32;   // warp n-offset in tile
    const int g  = lane >> 2;          // groupID
    const int tg = lane & 3;           // threadID_in_group

    float acc[4][4][4];
    #pragma unroll
    for (int i = 0; i < 4; i++)
        #pragma unroll
        for (int j = 0; j < 4; j++)
            #pragma unroll
            for (int r = 0; r < 4; r++) acc[i][j][r] = 0.f;

    // ---- tile loader ----
    auto load_tile = [&](int s, int k0) {
        // A tile -> As[s][k][m]
        if (MODE == 0 || MODE == 2) {          // A[M,K]
            #pragma unroll
            for (int t = 0; t < 2; t++) {
                int idx  = tid + t*256;
                int row  = idx >> 2;           // 0..127
                int kseg = (idx & 3) * 4;
                float4 v = *(const float4*)(A + (size_t)(m0 + row)*K + k0 + kseg);
                As[s][kseg+0][row] = f2tf(v.x);
                As[s][kseg+1][row] = f2tf(v.y);
                As[s][kseg+2][row] = f2tf(v.z);
                As[s][kseg+3][row] = f2tf(v.w);
            }
        } else {                               // MODE 1: A[K,M]
            #pragma unroll
            for (int t = 0; t < 2; t++) {
                int idx  = tid + t*256;
                int kk   = idx >> 5;           // 0..15
                int mseg = (idx & 31) * 4;
                float4 v = *(const float4*)(A + (size_t)(k0 + kk)*M + m0 + mseg);
                As[s][kk][mseg+0] = f2tf(v.x);
                As[s][kk][mseg+1] = f2tf(v.y);
                As[s][kk][mseg+2] = f2tf(v.z);
                As[s][kk][mseg+3] = f2tf(v.w);
            }
        }
        // B tile -> Bs[s][k][n]
        if (MODE == 0 || MODE == 1) {          // B[K,N]
            #pragma unroll
            for (int t = 0; t < 2; t++) {
                int idx  = tid + t*256;
                int kk   = idx >> 5;
                int nseg = (idx & 31) * 4;
                float4 v = *(const float4*)(B + (size_t)(k0 + kk)*N + n0 + nseg);
                Bs[s][kk][nseg+0] = f2tf(v.x);
                Bs[s][kk][nseg+1] = f2tf(v.y);
                Bs[s][kk][nseg+2] = f2tf(v.z);
                Bs[s][kk][nseg+3] = f2tf(v.w);
            }
        } else {                               // MODE 2: B[N,K]
            #pragma unroll
            for (int t = 0; t < 2; t++) {
                int idx  = tid + t*256;
                int row  = idx >> 2;           // n index 0..127
                int kseg = (idx & 3) * 4;
                float4 v = *(const float4*)(B + (size_t)(n0 + row)*K + k0 + kseg);
                Bs[s][kseg+0][row] = f2tf(v.x);
                Bs[s][kseg+1][row] = f2tf(v.y);
                Bs[s][kseg+2][row] = f2tf(v.z);
                Bs[s][kseg+3][row] = f2tf(v.w);
            }
        }
    };

    auto compute = [&](int s) {
        #pragma unroll
        for (int kk = 0; kk < 16; kk += 8) {
            uint32_t af[4][4], bf[4][2];
            #pragma unroll
            for (int mi = 0; mi < 4; mi++) {
                int r = wm + mi*16;
                af[mi][0] = As[s][kk+tg  ][r + g];
                af[mi][1] = As[s][kk+tg  ][r + g + 8];
                af[mi][2] = As[s][kk+tg+4][r + g];
                af[mi][3] = As[s][kk+tg+4][r + g + 8];
            }
            #pragma unroll
            for (int ni = 0; ni < 4; ni++) {
                int cl = wn + ni*8;
                bf[ni][0] = Bs[s][kk+tg  ][cl + g];
                bf[ni][1] = Bs[s][kk+tg+4][cl + g];
            }
            #pragma unroll
            for (int mi = 0; mi < 4; mi++)
                #pragma unroll
                for (int ni = 0; ni < 4; ni++)
                    mma_tf32(acc[mi][ni], af[mi], bf[ni]);
        }
    };

    load_tile(0, 0);
    __syncthreads();
    int s = 0;
    for (int k0 = 0; k0 < K; k0 += 16) {
        if (k0 + 16 < K) load_tile(s ^ 1, k0 + 16);
        compute(s);
        __syncthreads();
        s ^= 1;
    }

    // ---- epilogue ----
    #pragma unroll
    for (int mi = 0; mi < 4; mi++) {
        int row0 = m0 + wm + mi*16 + g;
        int row1 = row0 + 8;
        float b0 = BIAS ? bias[row0] : 0.f;
        float b1 = BIAS ? bias[row1] : 0.f;
        #pragma unroll
        for (int ni = 0; ni < 4; ni++) {
            int col = n0 + wn + ni*8 + 2*tg;
            float c0 = acc[mi][ni][0]*alpha + b0;
            float c1 = acc[mi][ni][1]*alpha + b0;
            float c2 = acc[mi][ni][2]*alpha + b1;
            float c3 = acc[mi][ni][3]*alpha + b1;
            if (RESID) {
                c0 += res[(size_t)row0*N + col];
                c1 += res[(size_t)row0*N + col + 1];
                c2 += res[(size_t)row1*N + col];
                c3 += res[(size_t)row1*N + col + 1];
            }
            *(float2*)(Cm + (size_t)row0*N + col) = make_float2(c0, c1);
            *(float2*)(Cm + (size_t)row1*N + col) = make_float2(c2, c3);
        }
    }
}

// ---------------- row softmax over g_s ----------------
__global__ void softmax_kernel()
{
    float* p = g_s + (size_t)blockIdx.x * NPIX;
    const int t = threadIdx.x;
    __shared__ float sh[256];

    float m = -1e30f;
    for (int i = t*4; i < NPIX; i += 1024) {
        float4 v = *(const float4*)(p + i);
        m = fmaxf(m, fmaxf(fmaxf(v.x, v.y), fmaxf(v.z, v.w)));
    }
    sh[t] = m; __syncthreads();
    for (int o = 128; o > 0; o >>= 1) {
        if (t < o) sh[t] = fmaxf(sh[t], sh[t+o]);
        __syncthreads();
    }
    m = sh[0]; __syncthreads();

    float s = 0.f;
    for (int i = t*4; i < NPIX; i += 1024) {
        float4 v = *(const float4*)(p + i);
        v.x = __expf(v.x - m); v.y = __expf(v.y - m);
        v.z = __expf(v.z - m); v.w = __expf(v.w - m);
        s += v.x + v.y + v.z + v.w;
        *(float4*)(p + i) = v;
    }
    sh[t] = s; __syncthreads();
    for (int o = 128; o > 0; o >>= 1) {
        if (t < o) sh[t] += sh[t+o];
        __syncthreads();
    }
    const float inv = 1.f / sh[0];

    for (int i = t*4; i < NPIX; i += 1024) {
        float4 v = *(const float4*)(p + i);
        v.x *= inv; v.y *= inv; v.z *= inv; v.w *= inv;
        *(float4*)(p + i) = v;
    }
}

// ---------------- launch ----------------
extern "C" void kernel_launch(void* const* d_in, const int* in_sizes, int n_in,
                              void* d_out, int out_size)
{
    const float* x     = (const float*)d_in[0];
    const float* gamma = (const float*)d_in[1];
    const float* beta  = (const float*)d_in[2];
    const float* wq    = (const float*)d_in[3];
    const float* bq    = (const float*)d_in[4];
    const float* wk    = (const float*)d_in[5];
    const float* bk    = (const float*)d_in[6];
    const float* wv    = (const float*)d_in[7];
    const float* bv    = (const float*)d_in[8];
    const float* wo    = (const float*)d_in[9];
    const float* bo    = (const float*)d_in[10];
    float* out = (float*)d_out;

    float *p_hn, *p_q, *p_k, *p_v, *p_o, *p_s;
    cudaGetSymbolAddress((void**)&p_hn, g_hn);
    cudaGetSymbolAddress((void**)&p_q,  g_q);
    cudaGetSymbolAddress((void**)&p_k,  g_k);
    cudaGetSymbolAddress((void**)&p_v,  g_v);
    cudaGetSymbolAddress((void**)&p_o,  g_o);
    cudaGetSymbolAddress((void**)&p_s,  g_s);

    const size_t sBC = (size_t)CH * NPIX;
    const size_t sS  = (size_t)NPIX * NPIX;
    const float scale = rsqrtf((float)CH);

    // 1. GroupNorm
    gn_kernel<<<dim3(GROUPS, BATCH), 256>>>(x, gamma, beta);

    // 2. q/k/v = W * hn + b   (NN: M=CH, N=NPIX, K=CH)
    dim3 gQKV(NPIX/128, CH/128, BATCH);
    gemm_tc<0, true, false><<<gQKV, 256>>>(wq, p_hn, p_q, bq, nullptr,
                                           CH, NPIX, CH, 0, sBC, sBC, 1.f);
    gemm_tc<0, true, false><<<gQKV, 256>>>(wk, p_hn, p_k, bk, nullptr,
                                           CH, NPIX, CH, 0, sBC, sBC, 1.f);
    gemm_tc<0, true, false><<<gQKV, 256>>>(wv, p_hn, p_v, bv, nullptr,
                                           CH, NPIX, CH, 0, sBC, sBC, 1.f);

    // 3. scores = scale * q^T k  (TN: M=NPIX, N=NPIX, K=CH)
    dim3 gS(NPIX/128, NPIX/128, BATCH);
    gemm_tc<1, false, false><<<gS, 256>>>(p_q, p_k, p_s, nullptr, nullptr,
                                          NPIX, NPIX, CH, sBC, sBC, sS, scale);

    // 4. softmax rows
    softmax_kernel<<<BATCH*NPIX, 256>>>();

    // 5. o = v * attn^T  (NT: M=CH, N=NPIX, K=NPIX)
    dim3 gO(NPIX/128, CH/128, BATCH);
    gemm_tc<2, false, false><<<gO, 256>>>(p_v, p_s, p_o, nullptr, nullptr,
                                          CH, NPIX, NPIX, sBC, sS, sBC, 1.f);

    // 6. out = wo * o + bo + x  (NN with residual)
    gemm_tc<0, true, true><<<gQKV, 256>>>(wo, p_o, out, bo, x,
                                          CH, NPIX, CH, 0, sBC, sBC, 1.f);
}

// round 3
// speedup vs baseline: 2.7488x; 1.1553x over previous
#include <cuda_runtime.h>
#include <math.h>
#include <stdint.h>

#define BATCH  2
#define CH     512
#define NPIX   4096      // 64*64
#define GROUPS 32
#define CPG    (CH/GROUPS)   // 16
#define EPS    1e-6f

// ---------------- scratch (device globals; no allocation) ----------------
__device__ float g_hn[(size_t)BATCH*CH*NPIX];
__device__ float g_q [(size_t)BATCH*CH*NPIX];
__device__ float g_k [(size_t)BATCH*CH*NPIX];
__device__ float g_v [(size_t)BATCH*CH*NPIX];
__device__ float g_o [(size_t)BATCH*CH*NPIX];
__device__ float g_s [(size_t)BATCH*NPIX*NPIX];   // exp(scores) (128 MiB)
__device__ float g_S [(size_t)BATCH*NPIX];        // row sums of exp(scores)

// ---------------- GroupNorm ----------------
__global__ void gn_kernel(const float* __restrict__ x,
                          const float* __restrict__ gamma,
                          const float* __restrict__ beta)
{
    const int b = blockIdx.y, g = blockIdx.x;
    const size_t base = ((size_t)b*CH + (size_t)g*CPG) * NPIX;
    const float* xp = x + base;
    float* hp = g_hn + base;
    const int NE = CPG * NPIX; // 65536

    float s = 0.f, ss = 0.f;
    for (int i = threadIdx.x*4; i < NE; i += blockDim.x*4) {
        float4 v = *(const float4*)(xp + i);
        s  += v.x + v.y + v.z + v.w;
        ss += v.x*v.x + v.y*v.y + v.z*v.z + v.w*v.w;
    }
    __shared__ float sh1[256], sh2[256];
    sh1[threadIdx.x] = s; sh2[threadIdx.x] = ss;
    __syncthreads();
    for (int o = 128; o > 0; o >>= 1) {
        if (threadIdx.x < o) {
            sh1[threadIdx.x] += sh1[threadIdx.x + o];
            sh2[threadIdx.x] += sh2[threadIdx.x + o];
        }
        __syncthreads();
    }
    const float mu  = sh1[0] / (float)NE;
    const float var = sh2[0] / (float)NE - mu*mu;
    const float inv = rsqrtf(var + EPS);

    for (int i = threadIdx.x*4; i < NE; i += blockDim.x*4) {
        int c = g*CPG + i / NPIX;
        float ga = gamma[c], be = beta[c];
        float4 v = *(const float4*)(xp + i);
        v.x = (v.x - mu)*inv*ga + be;
        v.y = (v.y - mu)*inv*ga + be;
        v.z = (v.z - mu)*inv*ga + be;
        v.w = (v.w - mu)*inv*ga + be;
        *(float4*)(hp + i) = v;
    }
}

// ---------------- zero the rowsum buffer ----------------
__global__ void zero_S_kernel()
{
    int i = blockIdx.x * blockDim.x + threadIdx.x;
    if (i < BATCH*NPIX) g_S[i] = 0.f;
}

// ---------------- tf32 helpers ----------------
__device__ __forceinline__ uint32_t f2tf(float x) {
    uint32_t r;
    asm("cvt.rna.tf32.f32 %0, %1;" : "=r"(r) : "f"(x));
    return r;
}

__device__ __forceinline__ void mma_tf32(float* c, const uint32_t* a, const uint32_t* b) {
    asm volatile(
        "mma.sync.aligned.m16n8k8.row.col.f32.tf32.tf32.f32 "
        "{%0,%1,%2,%3}, {%4,%5,%6,%7}, {%8,%9}, {%0,%1,%2,%3};"
        : "+f"(c[0]), "+f"(c[1]), "+f"(c[2]), "+f"(c[3])
        : "r"(a[0]), "r"(a[1]), "r"(a[2]), "r"(a[3]),
          "r"(b[0]), "r"(b[1]));
}

// ---------------- core tensor-core tf32 GEMM (device body) ----------------
// C[m,n] = alpha * sum_k Aop[m,k]*Bop[k,n]
// MODE 0 (NN): A[M,K], B[K,N]
// MODE 1 (TN): A[K,M], B[K,N]
// MODE 2 (NT): A[M,K], B[N,K]
// Block tile 128x128, BK=16, 256 threads (8 warps, 2m x 4n), warp tile 64x32.
// SCORES: store exp(alpha*acc), atomically accumulate row sums into rowsum.
// COLSCALE: multiply column n by 1/colsum[n] before bias/resid.
// SPAD=136: fragment LDS bank = (8*tg + g) mod 32 -> conflict-free.
#define SPAD 136
template<int MODE, bool BIAS, bool RESID, bool SCORES, bool COLSCALE>
__device__ __forceinline__ void gemm_core(
    const float* __restrict__ A, const float* __restrict__ B,
    float* __restrict__ Cm, const float* __restrict__ bias,
    const float* __restrict__ res, float* __restrict__ rowsum,
    const float* __restrict__ colsum,
    int M, int N, int K, float alpha, int m0, int n0)
{
    __shared__ uint32_t As[2][16][SPAD];
    __shared__ uint32_t Bs[2][16][SPAD];

    const int tid  = threadIdx.x;
    const int lane = tid & 31;
    const int warp = tid >> 5;
    const int wm = (warp & 1) * 64;
    const int wn = (warp >> 1) * 32;
    const int g  = lane >> 2;          // groupID (row within fragment)
    const int tg = lane & 3;           // thread in group (k / col pairs)

    float acc[4][4][4];
    #pragma unroll
    for (int i = 0; i < 4; i++)
        #pragma unroll
        for (int j = 0; j < 4; j++)
            #pragma unroll
            for (int r = 0; r < 4; r++) acc[i][j][r] = 0.f;

    auto load_tile = [&](int s, int k0) {
        // A tile -> As[s][k][m]
        if (MODE == 0 || MODE == 2) {          // A[M,K]
            #pragma unroll
            for (int t = 0; t < 2; t++) {
                int idx  = tid + t*256;
                int row  = idx >> 2;           // 0..127 (m)
                int kseg = (idx & 3) * 4;
                float4 v = *(const float4*)(A + (size_t)(m0 + row)*K + k0 + kseg);
                As[s][kseg+0][row] = f2tf(v.x);
                As[s][kseg+1][row] = f2tf(v.y);
                As[s][kseg+2][row] = f2tf(v.z);
                As[s][kseg+3][row] = f2tf(v.w);
            }
        } else {                               // MODE 1: A[K,M]
            #pragma unroll
            for (int t = 0; t < 2; t++) {
                int idx  = tid + t*256;
                int kk   = idx >> 5;           // 0..15
                int mseg = (idx & 31) * 4;
                float4 v = *(const float4*)(A + (size_t)(k0 + kk)*M + m0 + mseg);
                uint4 u = make_uint4(f2tf(v.x), f2tf(v.y), f2tf(v.z), f2tf(v.w));
                *(uint4*)&As[s][kk][mseg] = u;
            }
        }
        // B tile -> Bs[s][k][n]
        if (MODE == 0 || MODE == 1) {          // B[K,N]
            #pragma unroll
            for (int t = 0; t < 2; t++) {
                int idx  = tid + t*256;
                int kk   = idx >> 5;
                int nseg = (idx & 31) * 4;
                float4 v = *(const float4*)(B + (size_t)(k0 + kk)*N + n0 + nseg);
                uint4 u = make_uint4(f2tf(v.x), f2tf(v.y), f2tf(v.z), f2tf(v.w));
                *(uint4*)&Bs[s][kk][nseg] = u;
            }
        } else {                               // MODE 2: B[N,K]
            #pragma unroll
            for (int t = 0; t < 2; t++) {
                int idx  = tid + t*256;
                int row  = idx >> 2;           // 0..127 (n)
                int kseg = (idx & 3) * 4;
                float4 v = *(const float4*)(B + (size_t)(n0 + row)*K + k0 + kseg);
                Bs[s][kseg+0][row] = f2tf(v.x);
                Bs[s][kseg+1][row] = f2tf(v.y);
                Bs[s][kseg+2][row] = f2tf(v.z);
                Bs[s][kseg+3][row] = f2tf(v.w);
            }
        }
    };

    auto compute = [&](int s) {
        #pragma unroll
        for (int kk = 0; kk < 16; kk += 8) {
            uint32_t af[4][4], bf[4][2];
            #pragma unroll
            for (int mi = 0; mi < 4; mi++) {
                int r = wm + mi*16;
                af[mi][0] = As[s][kk+tg  ][r + g];
                af[mi][1] = As[s][kk+tg  ][r + g + 8];
                af[mi][2] = As[s][kk+tg+4][r + g];
                af[mi][3] = As[s][kk+tg+4][r + g + 8];
            }
            #pragma unroll
            for (int ni = 0; ni < 4; ni++) {
                int cl = wn + ni*8;
                bf[ni][0] = Bs[s][kk+tg  ][cl + g];
                bf[ni][1] = Bs[s][kk+tg+4][cl + g];
            }
            #pragma unroll
            for (int mi = 0; mi < 4; mi++)
                #pragma unroll
                for (int ni = 0; ni < 4; ni++)
                    mma_tf32(acc[mi][ni], af[mi], bf[ni]);
        }
    };

    load_tile(0, 0);
    __syncthreads();
    int s = 0;
    for (int k0 = 0; k0 < K; k0 += 16) {
        if (k0 + 16 < K) load_tile(s ^ 1, k0 + 16);
        compute(s);
        __syncthreads();
        s ^= 1;
    }

    // ---- epilogue ----
    #pragma unroll
    for (int mi = 0; mi < 4; mi++) {
        int row0 = m0 + wm + mi*16 + g;
        int row1 = row0 + 8;
        float b0 = BIAS ? bias[row0] : 0.f;
        float b1 = BIAS ? bias[row1] : 0.f;
        float sum0 = 0.f, sum1 = 0.f;
        #pragma unroll
        for (int ni = 0; ni < 4; ni++) {
            int col = n0 + wn + ni*8 + 2*tg;
            float c0 = acc[mi][ni][0]*alpha;
            float c1 = acc[mi][ni][1]*alpha;
            float c2 = acc[mi][ni][2]*alpha;
            float c3 = acc[mi][ni][3]*alpha;
            if (SCORES) {
                c0 = __expf(c0); c1 = __expf(c1);
                c2 = __expf(c2); c3 = __expf(c3);
                sum0 += c0 + c1;
                sum1 += c2 + c3;
            }
            if (COLSCALE) {
                float i0 = __fdividef(1.f, colsum[col]);
                float i1 = __fdividef(1.f, colsum[col + 1]);
                c0 *= i0; c1 *= i1; c2 *= i0; c3 *= i1;
            }
            c0 += b0; c1 += b0; c2 += b1; c3 += b1;
            if (RESID) {
                c0 += res[(size_t)row0*N + col];
                c1 += res[(size_t)row0*N + col + 1];
                c2 += res[(size_t)row1*N + col];
                c3 += res[(size_t)row1*N + col + 1];
            }
            *(float2*)(Cm + (size_t)row0*N + col) = make_float2(c0, c1);
            *(float2*)(Cm + (size_t)row1*N + col) = make_float2(c2, c3);
        }
        if (SCORES) {
            // reduce across the 4 tg lanes (same g => same rows)
            sum0 += __shfl_xor_sync(0xffffffffu, sum0, 1);
            sum0 += __shfl_xor_sync(0xffffffffu, sum0, 2);
            sum1 += __shfl_xor_sync(0xffffffffu, sum1, 1);
            sum1 += __shfl_xor_sync(0xffffffffu, sum1, 2);
            if (tg == 0) {
                atomicAdd(rowsum + row0, sum0);
                atomicAdd(rowsum + row1, sum1);
            }
        }
    }
}

// ---------------- kernel wrappers ----------------
static const size_t sBC = (size_t)CH * NPIX;
static const size_t sS  = (size_t)NPIX * NPIX;

// fused q/k/v: grid (NPIX/128, 3*CH/128, BATCH)
__global__ __launch_bounds__(256, 2)
void qkv_kernel(const float* __restrict__ hn,
                const float* __restrict__ wq, const float* __restrict__ bq,
                const float* __restrict__ wk, const float* __restrict__ bk,
                const float* __restrict__ wv, const float* __restrict__ bv,
                float* __restrict__ q, float* __restrict__ k, float* __restrict__ v)
{
    const int sel = blockIdx.y >> 2;          // 0=q 1=k 2=v (CH/128 = 4)
    const int my  = blockIdx.y & 3;
    const int bz  = blockIdx.z;
    const float* W  = sel == 0 ? wq : sel == 1 ? wk : wv;
    const float* bb = sel == 0 ? bq : sel == 1 ? bk : bv;
    float* C        = sel == 0 ? q  : sel == 1 ? k  : v;
    gemm_core<0, true, false, false, false>(
        W, hn + bz*sBC, C + bz*sBC, bb, nullptr, nullptr, nullptr,
        CH, NPIX, CH, 1.f, my*128, blockIdx.x*128);
}

// scores: e = exp(scale * q^T k), rowsum accumulated. grid (32, 32, BATCH)
__global__ __launch_bounds__(256, 2)
void scores_kernel(const float* __restrict__ q, const float* __restrict__ k,
                   float scale)
{
    const int bz = blockIdx.z;
    gemm_core<1, false, false, true, false>(
        q + bz*sBC, k + bz*sBC, g_s + bz*sS, nullptr, nullptr,
        g_S + bz*NPIX, nullptr,
        NPIX, NPIX, CH, scale, blockIdx.y*128, blockIdx.x*128);
}

// o_un = v * e^T. grid (32, 4, BATCH)
__global__ __launch_bounds__(256, 2)
void av_kernel(const float* __restrict__ v)
{
    const int bz = blockIdx.z;
    gemm_core<2, false, false, false, false>(
        v + bz*sBC, g_s + bz*sS, g_o + bz*sBC, nullptr, nullptr, nullptr, nullptr,
        CH, NPIX, NPIX, 1.f, blockIdx.y*128, blockIdx.x*128);
}

// out = (wo * o_un) / S + bo + x. grid (32, 4, BATCH)
__global__ __launch_bounds__(256, 2)
void outconv_kernel(const float* __restrict__ wo, const float* __restrict__ bo,
                    const float* __restrict__ x, float* __restrict__ out)
{
    const int bz = blockIdx.z;
    gemm_core<0, true, true, false, true>(
        wo, g_o + bz*sBC, out + bz*sBC, bo, x + bz*sBC, nullptr, g_S + bz*NPIX,
        CH, NPIX, CH, 1.f, blockIdx.y*128, blockIdx.x*128);
}

// ---------------- launch ----------------
extern "C" void kernel_launch(void* const* d_in, const int* in_sizes, int n_in,
                              void* d_out, int out_size)
{
    const float* x     = (const float*)d_in[0];
    const float* gamma = (const float*)d_in[1];
    const float* beta  = (const float*)d_in[2];
    const float* wq    = (const float*)d_in[3];
    const float* bq    = (const float*)d_in[4];
    const float* wk    = (const float*)d_in[5];
    const float* bk    = (const float*)d_in[6];
    const float* wv    = (const float*)d_in[7];
    const float* bv    = (const float*)d_in[8];
    const float* wo    = (const float*)d_in[9];
    const float* bo    = (const float*)d_in[10];
    float* out = (float*)d_out;

    float *p_hn, *p_q, *p_k, *p_v;
    cudaGetSymbolAddress((void**)&p_hn, g_hn);
    cudaGetSymbolAddress((void**)&p_q,  g_q);
    cudaGetSymbolAddress((void**)&p_k,  g_k);
    cudaGetSymbolAddress((void**)&p_v,  g_v);

    const float scale = rsqrtf((float)CH);

    // 1. GroupNorm + zero row sums (independent)
    gn_kernel<<<dim3(GROUPS, BATCH), 256>>>(x, gamma, beta);
    zero_S_kernel<<<(BATCH*NPIX + 255)/256, 256>>>();

    // 2. fused q/k/v
    qkv_kernel<<<dim3(NPIX/128, 3*(CH/128), BATCH), 256>>>(
        p_hn, wq, bq, wk, bk, wv, bv, p_q, p_k, p_v);

    // 3. e = exp(scale * q^T k), row sums via atomics
    scores_kernel<<<dim3(NPIX/128, NPIX/128, BATCH), 256>>>(p_q, p_k, scale);

    // 4. o_un = v * e^T
    av_kernel<<<dim3(NPIX/128, CH/128, BATCH), 256>>>(p_v);

    // 5. out = (wo * o_un)/S + bo + x
    outconv_kernel<<<dim3(NPIX/128, CH/128, BATCH), 256>>>(wo, bo, x, out);
}

// round 4
// speedup vs baseline: 3.8168x; 1.3885x over previous
#include <cuda_runtime.h>
#include <math.h>
#include <stdint.h>

#define BATCH  2
#define CH     512
#define NPIX   4096      // 64*64
#define GROUPS 32
#define CPG    (CH/GROUPS)   // 16
#define EPS    1e-6f
#define STAGES 3

// ---------------- scratch (device globals; no allocation) ----------------
__device__ float g_hn[(size_t)BATCH*CH*NPIX];
__device__ float g_q [(size_t)BATCH*CH*NPIX];
__device__ float g_k [(size_t)BATCH*CH*NPIX];
__device__ float g_v [(size_t)BATCH*CH*NPIX];
__device__ float g_o [(size_t)BATCH*CH*NPIX];
__device__ float g_s [(size_t)BATCH*NPIX*NPIX];   // exp(scores) (128 MiB)
__device__ float g_S [(size_t)BATCH*NPIX];        // row sums of exp(scores)

// ---------------- GroupNorm ----------------
__global__ void gn_kernel(const float* __restrict__ x,
                          const float* __restrict__ gamma,
                          const float* __restrict__ beta)
{
    const int b = blockIdx.y, g = blockIdx.x;
    const size_t base = ((size_t)b*CH + (size_t)g*CPG) * NPIX;
    const float* xp = x + base;
    float* hp = g_hn + base;
    const int NE = CPG * NPIX; // 65536

    float s = 0.f, ss = 0.f;
    for (int i = threadIdx.x*4; i < NE; i += blockDim.x*4) {
        float4 v = *(const float4*)(xp + i);
        s  += v.x + v.y + v.z + v.w;
        ss += v.x*v.x + v.y*v.y + v.z*v.z + v.w*v.w;
    }
    __shared__ float sh1[256], sh2[256];
    sh1[threadIdx.x] = s; sh2[threadIdx.x] = ss;
    __syncthreads();
    for (int o = 128; o > 0; o >>= 1) {
        if (threadIdx.x < o) {
            sh1[threadIdx.x] += sh1[threadIdx.x + o];
            sh2[threadIdx.x] += sh2[threadIdx.x + o];
        }
        __syncthreads();
    }
    const float mu  = sh1[0] / (float)NE;
    const float var = sh2[0] / (float)NE - mu*mu;
    const float inv = rsqrtf(var + EPS);

    for (int i = threadIdx.x*4; i < NE; i += blockDim.x*4) {
        int c = g*CPG + i / NPIX;
        float ga = gamma[c], be = beta[c];
        float4 v = *(const float4*)(xp + i);
        v.x = (v.x - mu)*inv*ga + be;
        v.y = (v.y - mu)*inv*ga + be;
        v.z = (v.z - mu)*inv*ga + be;
        v.w = (v.w - mu)*inv*ga + be;
        *(float4*)(hp + i) = v;
    }
}

__global__ void zero_S_kernel()
{
    int i = blockIdx.x * blockDim.x + threadIdx.x;
    if (i < BATCH*NPIX) g_S[i] = 0.f;
}

// ---------------- low-level helpers ----------------
__device__ __forceinline__ uint32_t smem_u32(const void* p) {
    return (uint32_t)__cvta_generic_to_shared(p);
}
__device__ __forceinline__ void cp16(uint32_t dst, const float* src) {
    asm volatile("cp.async.cg.shared.global [%0], [%1], 16;" :: "r"(dst), "l"(src));
}
__device__ __forceinline__ void mma_tf32(float* c, const uint32_t* a, const uint32_t* b) {
    asm volatile(
        "mma.sync.aligned.m16n8k8.row.col.f32.tf32.tf32.f32 "
        "{%0,%1,%2,%3}, {%4,%5,%6,%7}, {%8,%9}, {%0,%1,%2,%3};"
        : "+f"(c[0]), "+f"(c[1]), "+f"(c[2]), "+f"(c[3])
        : "r"(a[0]), "r"(a[1]), "r"(a[2]), "r"(a[3]),
          "r"(b[0]), "r"(b[1]));
}
__device__ __forceinline__ uint32_t fb(float x) { return __float_as_uint(x); }

// ---------------- tensor-core tf32 GEMM core ----------------
// C[m,n] = alpha * sum_k Aop[m,k]*Bop[k,n]
// AMODE 0: A[K,M] global (K-major rows of length M) -> smem As[k][m], pitch 136
// AMODE 1: A[M,K] global                             -> smem As[m][k], pitch 20
// BMODE 0: B[K,N] global -> Bs[k][n], pitch 136
// BMODE 1: B[N,K] global -> Bs[n][k], pitch 20
// Block tile 128x128, BK=16, 256 threads (8 warps, 2m x 4n), warp tile 64x32.
// 3-stage cp.async pipeline. Raw fp32 bits fed to tf32 MMA (HW truncation).
template<int AMODE, int BMODE, bool BIAS, bool RESID, bool SCORES, bool COLSCALE>
__device__ __forceinline__ void gemm_core(
    const float* __restrict__ A, const float* __restrict__ B,
    float* __restrict__ Cm, const float* __restrict__ bias,
    const float* __restrict__ res, float* __restrict__ rowsum,
    const float* __restrict__ colsum,
    int M, int N, int K, float alpha, int m0, int n0)
{
    constexpr int AW = (AMODE == 0) ? 16*136 : 128*20;   // words per A stage
    constexpr int BW = (BMODE == 0) ? 16*136 : 128*20;
    extern __shared__ float smem[];
    float* Asm = smem;
    float* Bsm = smem + STAGES*AW;

    const int lda = (AMODE == 0) ? M : K;
    const int ldb = (BMODE == 0) ? N : K;

    const int tid  = threadIdx.x;
    const int lane = tid & 31;
    const int warp = tid >> 5;
    const int wm = (warp & 1) * 64;
    const int wn = (warp >> 1) * 32;
    const int g  = lane >> 2;
    const int tg = lane & 3;

    float acc[4][4][4];
    #pragma unroll
    for (int i = 0; i < 4; i++)
        #pragma unroll
        for (int j = 0; j < 4; j++)
            #pragma unroll
            for (int r = 0; r < 4; r++) acc[i][j][r] = 0.f;

    auto load_tile = [&](int s, int k0) {
        float* Ab = Asm + s*AW;
        float* Bb = Bsm + s*BW;
        if (AMODE == 0) {
            #pragma unroll
            for (int t = 0; t < 2; t++) {
                int idx = tid + t*256;
                int kk = idx >> 5, mseg = (idx & 31) * 4;
                cp16(smem_u32(Ab + kk*136 + mseg),
                     A + (size_t)(k0 + kk)*lda + m0 + mseg);
            }
        } else {
            #pragma unroll
            for (int t = 0; t < 2; t++) {
                int idx = tid + t*256;
                int row = idx >> 2, kseg = (idx & 3) * 4;
                cp16(smem_u32(Ab + row*20 + kseg),
                     A + (size_t)(m0 + row)*lda + k0 + kseg);
            }
        }
        if (BMODE == 0) {
            #pragma unroll
            for (int t = 0; t < 2; t++) {
                int idx = tid + t*256;
                int kk = idx >> 5, nseg = (idx & 31) * 4;
                cp16(smem_u32(Bb + kk*136 + nseg),
                     B + (size_t)(k0 + kk)*ldb + n0 + nseg);
            }
        } else {
            #pragma unroll
            for (int t = 0; t < 2; t++) {
                int idx = tid + t*256;
                int row = idx >> 2, kseg = (idx & 3) * 4;
                cp16(smem_u32(Bb + row*20 + kseg),
                     B + (size_t)(n0 + row)*ldb + k0 + kseg);
            }
        }
    };

    auto compute = [&](int s) {
        const float* Ab = Asm + s*AW;
        const float* Bb = Bsm + s*BW;
        #pragma unroll
        for (int kk = 0; kk < 16; kk += 8) {
            uint32_t af[4][4], bf[4][2];
            #pragma unroll
            for (int mi = 0; mi < 4; mi++) {
                int r = wm + mi*16 + g;
                if (AMODE == 0) {
                    af[mi][0] = fb(Ab[(kk+tg  )*136 + r]);
                    af[mi][1] = fb(Ab[(kk+tg  )*136 + r + 8]);
                    af[mi][2] = fb(Ab[(kk+tg+4)*136 + r]);
                    af[mi][3] = fb(Ab[(kk+tg+4)*136 + r + 8]);
                } else {
                    af[mi][0] = fb(Ab[(r    )*20 + kk+tg]);
                    af[mi][1] = fb(Ab[(r + 8)*20 + kk+tg]);
                    af[mi][2] = fb(Ab[(r    )*20 + kk+tg+4]);
                    af[mi][3] = fb(Ab[(r + 8)*20 + kk+tg+4]);
                }
            }
            #pragma unroll
            for (int ni = 0; ni < 4; ni++) {
                int cl = wn + ni*8 + g;
                if (BMODE == 0) {
                    bf[ni][0] = fb(Bb[(kk+tg  )*136 + cl]);
                    bf[ni][1] = fb(Bb[(kk+tg+4)*136 + cl]);
                } else {
                    bf[ni][0] = fb(Bb[cl*20 + kk+tg]);
                    bf[ni][1] = fb(Bb[cl*20 + kk+tg+4]);
                }
            }
            #pragma unroll
            for (int mi = 0; mi < 4; mi++)
                #pragma unroll
                for (int ni = 0; ni < 4; ni++)
                    mma_tf32(acc[mi][ni], af[mi], bf[ni]);
        }
    };

    // ---- 3-stage pipeline ----
    load_tile(0, 0);
    asm volatile("cp.async.commit_group;" ::: "memory");
    load_tile(1, 16);
    asm volatile("cp.async.commit_group;" ::: "memory");

    int rd = 0;
    for (int k0 = 0; k0 < K; k0 += 16) {
        asm volatile("cp.async.wait_group 1;" ::: "memory");
        __syncthreads();
        int kn = k0 + 32;
        if (kn < K) {
            int ws = rd + 2; if (ws >= STAGES) ws -= STAGES;
            load_tile(ws, kn);
        }
        asm volatile("cp.async.commit_group;" ::: "memory");
        compute(rd);
        rd++; if (rd >= STAGES) rd = 0;
    }

    // ---- epilogue ----
    #pragma unroll
    for (int mi = 0; mi < 4; mi++) {
        int row0 = m0 + wm + mi*16 + g;
        int row1 = row0 + 8;
        float b0 = BIAS ? bias[row0] : 0.f;
        float b1 = BIAS ? bias[row1] : 0.f;
        float sum0 = 0.f, sum1 = 0.f;
        #pragma unroll
        for (int ni = 0; ni < 4; ni++) {
            int col = n0 + wn + ni*8 + 2*tg;
            float c0 = acc[mi][ni][0]*alpha;
            float c1 = acc[mi][ni][1]*alpha;
            float c2 = acc[mi][ni][2]*alpha;
            float c3 = acc[mi][ni][3]*alpha;
            if (SCORES) {
                c0 = __expf(c0); c1 = __expf(c1);
                c2 = __expf(c2); c3 = __expf(c3);
                sum0 += c0 + c1;
                sum1 += c2 + c3;
            }
            if (COLSCALE) {
                float i0 = __fdividef(1.f, colsum[col]);
                float i1 = __fdividef(1.f, colsum[col + 1]);
                c0 *= i0; c1 *= i1; c2 *= i0; c3 *= i1;
            }
            c0 += b0; c1 += b0; c2 += b1; c3 += b1;
            if (RESID) {
                c0 += res[(size_t)row0*N + col];
                c1 += res[(size_t)row0*N + col + 1];
                c2 += res[(size_t)row1*N + col];
                c3 += res[(size_t)row1*N + col + 1];
            }
            *(float2*)(Cm + (size_t)row0*N + col) = make_float2(c0, c1);
            *(float2*)(Cm + (size_t)row1*N + col) = make_float2(c2, c3);
        }
        if (SCORES) {
            sum0 += __shfl_xor_sync(0xffffffffu, sum0, 1);
            sum0 += __shfl_xor_sync(0xffffffffu, sum0, 2);
            sum1 += __shfl_xor_sync(0xffffffffu, sum1, 1);
            sum1 += __shfl_xor_sync(0xffffffffu, sum1, 2);
            if (tg == 0) {
                atomicAdd(rowsum + row0, sum0);
                atomicAdd(rowsum + row1, sum1);
            }
        }
    }
}

// ---------------- kernel wrappers ----------------
static const size_t sBC = (size_t)CH * NPIX;
static const size_t sS  = (size_t)NPIX * NPIX;

// smem sizes (bytes) per kernel
#define SMEM_A0 (16*136*4)
#define SMEM_A1 (128*20*4)
#define SMEM_QKV   (STAGES*(SMEM_A1 + SMEM_A0))   // A1 + B0
#define SMEM_SCO   (STAGES*(SMEM_A0 + SMEM_A0))   // A0 + B0
#define SMEM_AV    (STAGES*(SMEM_A1 + SMEM_A1))   // A1 + B1
#define SMEM_OUT   (STAGES*(SMEM_A1 + SMEM_A0))   // A1 + B0

// fused q/k/v: grid (NPIX/128, 3*CH/128, BATCH)  — W is A[M,K], hn is B[K,N]
__global__ __launch_bounds__(256, 2)
void qkv_kernel(const float* __restrict__ hn,
                const float* __restrict__ wq, const float* __restrict__ bq,
                const float* __restrict__ wk, const float* __restrict__ bk,
                const float* __restrict__ wv, const float* __restrict__ bv,
                float* __restrict__ q, float* __restrict__ k, float* __restrict__ v)
{
    const int sel = blockIdx.y >> 2;          // 0=q 1=k 2=v (CH/128 = 4)
    const int my  = blockIdx.y & 3;
    const int bz  = blockIdx.z;
    const float* W  = sel == 0 ? wq : sel == 1 ? wk : wv;
    const float* bb = sel == 0 ? bq : sel == 1 ? bk : bv;
    float* C        = sel == 0 ? q  : sel == 1 ? k  : v;
    gemm_core<1, 0, true, false, false, false>(
        W, hn + bz*sBC, C + bz*sBC, bb, nullptr, nullptr, nullptr,
        CH, NPIX, CH, 1.f, my*128, blockIdx.x*128);
}

// scores: e = exp(scale * q^T k). q is A[K,M], k is B[K,N]. grid (32,32,BATCH)
__global__ __launch_bounds__(256, 2)
void scores_kernel(const float* __restrict__ q, const float* __restrict__ k,
                   float scale)
{
    const int bz = blockIdx.z;
    gemm_core<0, 0, false, false, true, false>(
        q + bz*sBC, k + bz*sBC, g_s + bz*sS, nullptr, nullptr,
        g_S + bz*NPIX, nullptr,
        NPIX, NPIX, CH, scale, blockIdx.y*128, blockIdx.x*128);
}

// o_un = v * e^T. v is A[M,K], e is B[N,K]. grid (32, 4, BATCH)
__global__ __launch_bounds__(256, 2)
void av_kernel(const float* __restrict__ v)
{
    const int bz = blockIdx.z;
    gemm_core<1, 1, false, false, false, false>(
        v + bz*sBC, g_s + bz*sS, g_o + bz*sBC, nullptr, nullptr, nullptr, nullptr,
        CH, NPIX, NPIX, 1.f, blockIdx.y*128, blockIdx.x*128);
}

// out = (wo * o_un)/S + bo + x. grid (32, 4, BATCH)
__global__ __launch_bounds__(256, 2)
void outconv_kernel(const float* __restrict__ wo, const float* __restrict__ bo,
                    const float* __restrict__ x, float* __restrict__ out)
{
    const int bz = blockIdx.z;
    gemm_core<1, 0, true, true, false, true>(
        wo, g_o + bz*sBC, out + bz*sBC, bo, x + bz*sBC, nullptr, g_S + bz*NPIX,
        CH, NPIX, CH, 1.f, blockIdx.y*128, blockIdx.x*128);
}

// ---------------- launch ----------------
extern "C" void kernel_launch(void* const* d_in, const int* in_sizes, int n_in,
                              void* d_out, int out_size)
{
    const float* x     = (const float*)d_in[0];
    const float* gamma = (const float*)d_in[1];
    const float* beta  = (const float*)d_in[2];
    const float* wq    = (const float*)d_in[3];
    const float* bq    = (const float*)d_in[4];
    const float* wk    = (const float*)d_in[5];
    const float* bk    = (const float*)d_in[6];
    const float* wv    = (const float*)d_in[7];
    const float* bv    = (const float*)d_in[8];
    const float* wo    = (const float*)d_in[9];
    const float* bo    = (const float*)d_in[10];
    float* out = (float*)d_out;

    float *p_hn, *p_q, *p_k, *p_v;
    cudaGetSymbolAddress((void**)&p_hn, g_hn);
    cudaGetSymbolAddress((void**)&p_q,  g_q);
    cudaGetSymbolAddress((void**)&p_k,  g_k);
    cudaGetSymbolAddress((void**)&p_v,  g_v);

    cudaFuncSetAttribute(qkv_kernel,    cudaFuncAttributeMaxDynamicSharedMemorySize, SMEM_QKV);
    cudaFuncSetAttribute(scores_kernel, cudaFuncAttributeMaxDynamicSharedMemorySize, SMEM_SCO);
    cudaFuncSetAttribute(av_kernel,     cudaFuncAttributeMaxDynamicSharedMemorySize, SMEM_AV);
    cudaFuncSetAttribute(outconv_kernel,cudaFuncAttributeMaxDynamicSharedMemorySize, SMEM_OUT);

    const float scale = rsqrtf((float)CH);

    // 1. GroupNorm + zero row sums
    gn_kernel<<<dim3(GROUPS, BATCH), 256>>>(x, gamma, beta);
    zero_S_kernel<<<(BATCH*NPIX + 255)/256, 256>>>();

    // 2. fused q/k/v
    qkv_kernel<<<dim3(NPIX/128, 3*(CH/128), BATCH), 256, SMEM_QKV>>>(
        p_hn, wq, bq, wk, bk, wv, bv, p_q, p_k, p_v);

    // 3. e = exp(scale * q^T k), row sums via atomics
    scores_kernel<<<dim3(NPIX/128, NPIX/128, BATCH), 256, SMEM_SCO>>>(p_q, p_k, scale);

    // 4. o_un = v * e^T
    av_kernel<<<dim3(NPIX/128, CH/128, BATCH), 256, SMEM_AV>>>(p_v);

    // 5. out = (wo * o_un)/S + bo + x
    outconv_kernel<<<dim3(NPIX/128, CH/128, BATCH), 256, SMEM_OUT>>>(wo, bo, x, out);
}